// round 5
// baseline (speedup 1.0000x reference)
#include <cuda_runtime.h>

// EMA scan: y_t = d*x_t + (1-d)*y_{t-1}, y_{-1} = x[0], d = 0.9 (a = 0.1).
//
// CHUNK = 4 = one float4 per thread -> perfectly coalesced LDG/STG, NO smem
// data staging. Chunk transfer map is y -> a^4*y + S with constant a^4, so a
// 3-step constant-coefficient warp scan (coeffs a^4, a^8, a^16) gives every
// lane a 32-element lookback (truncation a^32 ~ 1e-32, below fp32 eps).
// Warp->warp: a^128 underflows to 0, so warp carries are independent; one
// tiny smem exchange. Block seed: warp 0 scans a 32-element gmem halo.

#define NT   256
#define NW   (NT / 32)
#define TILE (NT * 4)        // 1024 elements per block

__global__ __launch_bounds__(NT)
void ema_kernel(const float* __restrict__ x,
                const float* __restrict__ decay_p,
                float* __restrict__ out, int n)
{
    __shared__ float warpS[NW];

    const float d   = __ldg(decay_p);
    const float a   = 1.0f - d;
    const float a2  = a * a;
    const float p4  = a2 * a2;     // a^4
    const float p8  = p4 * p4;     // a^8
    const float p16 = p8 * p8;     // a^16

    const int tid   = threadIdx.x;
    const int lane  = tid & 31;
    const int wid   = tid >> 5;
    const int tile0 = blockIdx.x * TILE;
    const int g     = tile0 + 4 * tid;

    // ---- load own chunk (one coalesced LDG.128) ----
    float4 v;
    if (g + 3 < n) {
        v = __ldcs(reinterpret_cast<const float4*>(x + g));
    } else {
        v.x = (g + 0 < n) ? x[g + 0] : 0.0f;
        v.y = (g + 1 < n) ? x[g + 1] : 0.0f;
        v.z = (g + 2 < n) ? x[g + 2] : 0.0f;
        v.w = (g + 3 < n) ? x[g + 3] : 0.0f;
    }

    // ---- chunk sum: S = d*(v.w + a*v.z + a^2*v.y + a^3*v.x) ----
    float h = v.x;
    h = fmaf(a, h, v.y);
    h = fmaf(a, h, v.z);
    h = fmaf(a, h, v.w);
    float S = d * h;

    // ---- 3-step constant-coefficient inclusive warp scan (lookback 8 chunks) ----
    float t;
    t = __shfl_up_sync(0xffffffffu, S, 1);
    if (lane >= 1) S = fmaf(p4, t, S);
    t = __shfl_up_sync(0xffffffffu, S, 2);
    if (lane >= 2) S = fmaf(p8, t, S);
    t = __shfl_up_sync(0xffffffffu, S, 4);
    if (lane >= 4) S = fmaf(p16, t, S);

    // ---- warp carry out: inclusive S of lane 31 (a^128 kills anything older) ----
    if (lane == 31) warpS[wid] = S;

    // ---- block seed: warp 0 scans the 32-element gmem halo ----
    float seed = 0.0f;
    if (wid == 0) {
        if (blockIdx.x == 0) {
            seed = x[0];                         // exact: y_{-1} = x[0]
        } else {
            float hS = 0.0f;
            if (lane < 8) {
                const float4 hv = *reinterpret_cast<const float4*>(
                    x + tile0 - 32 + 4 * lane);
                float hh = hv.x;
                hh = fmaf(a, hh, hv.y);
                hh = fmaf(a, hh, hv.z);
                hh = fmaf(a, hh, hv.w);
                hS = d * hh;
            }
            float m;
            m = __shfl_up_sync(0xffffffffu, hS, 1);
            if (lane >= 1) hS = fmaf(p4, m, hS);
            m = __shfl_up_sync(0xffffffffu, hS, 2);
            if (lane >= 2) hS = fmaf(p8, m, hS);
            m = __shfl_up_sync(0xffffffffu, hS, 4);
            if (lane >= 4) hS = fmaf(p16, m, hS);
            seed = __shfl_sync(0xffffffffu, hS, 7);   // carry entering the tile
        }
    }
    __syncthreads();

    // ---- incoming carry for this thread ----
    float cw = (wid == 0) ? seed : warpS[wid - 1];

    // exclusive scan value (chunks i-8..i-1)
    float E = __shfl_up_sync(0xffffffffu, S, 1);
    if (lane == 0) E = 0.0f;

    // f = p4^lane via square-and-multiply (underflows to 0 for lane >= 16)
    float f = 1.0f, b = p4;
    if (lane & 1)  f *= b;  b *= b;     // a^8
    if (lane & 2)  f *= b;  b *= b;     // a^16
    if (lane & 4)  f *= b;  b *= b;     // a^32
    if (lane & 8)  f *= b;  b *= b;     // a^64 -> 0
    if (lane & 16) f *= b;

    float c = fmaf(f, cw, E);           // carry entering own chunk

    // ---- local 4-element recurrence ----
    float y0 = fmaf(a, c,  d * v.x);
    float y1 = fmaf(a, y0, d * v.y);
    float y2 = fmaf(a, y1, d * v.z);
    float y3 = fmaf(a, y2, d * v.w);

    // ---- store (one coalesced STG.128) ----
    if (g + 3 < n) {
        __stcs(reinterpret_cast<float4*>(out + g), make_float4(y0, y1, y2, y3));
    } else {
        if (g + 0 < n) out[g + 0] = y0;
        if (g + 1 < n) out[g + 1] = y1;
        if (g + 2 < n) out[g + 2] = y2;
        if (g + 3 < n) out[g + 3] = y3;
    }
}

extern "C" void kernel_launch(void* const* d_in, const int* in_sizes, int n_in,
                              void* d_out, int out_size)
{
    const float* x     = (const float*)d_in[0];
    const float* decay = (const float*)d_in[1];
    float*       out   = (float*)d_out;
    const int    n     = in_sizes[0];

    const int nblocks = (n + TILE - 1) / TILE;
    ema_kernel<<<nblocks, NT>>>(x, decay, out, n);
}

// round 6
// speedup vs baseline: 1.2632x; 1.2632x over previous
#include <cuda_runtime.h>

// EMA scan: y_t = d*x_t + (1-d)*y_{t-1}, y_{-1} = x[0], d = 0.9 (a = 0.1).
//
// Warp-independent design, zero smem / zero barriers:
//  - Each warp owns 1024 consecutive elements = 8 rows x (32 lanes x float4).
//  - All 8 row loads + 1 halo load issued up front -> MLP = 9 per warp.
//  - Row scan: 4-FMA Horner + 3-step constant-coeff Kogge-Stone (a^4,a^8,a^16)
//    gives each lane a 32-element lookback (a^32 ~ 1e-32, below fp32 eps).
//  - Row carry_out = lane-31 inclusive value (a^128 == 0), independent of
//    carry_in -> all row scans are ILP-parallel; carry chain is 1 shfl/row.
//  - Warp seed: 32-element gmem halo (lanes 0-7), ~3% extra read traffic.

#define NT    256
#define ROWS  8
#define ROWE  128                 // elements per row (32 lanes * 4)
#define WREG  (ROWS * ROWE)       // 1024 elements per warp
#define TILE  ((NT / 32) * WREG)  // 8192 elements per block

__device__ __forceinline__ float horner4(float a, float4 v) {
    float h = v.x;
    h = fmaf(a, h, v.y);
    h = fmaf(a, h, v.z);
    h = fmaf(a, h, v.w);
    return h;
}

__global__ __launch_bounds__(NT)
void ema_kernel(const float* __restrict__ x,
                const float* __restrict__ decay_p,
                float* __restrict__ out, int n)
{
    const float d   = __ldg(decay_p);
    const float a   = 1.0f - d;
    const float a2  = a * a;
    const float p4  = a2 * a2;
    const float p8  = p4 * p4;
    const float p16 = p8 * p8;

    const int lane = threadIdx.x & 31;
    const int wid  = threadIdx.x >> 5;
    const long wbase = (long)blockIdx.x * TILE + (long)wid * WREG;
    const bool full  = (wbase + WREG) <= (long)n;
    const bool first = (wbase == 0);

    // ---- issue all loads up front: halo + 8 rows (MLP = 9) ----
    float4 hv = make_float4(0.f, 0.f, 0.f, 0.f);
    if (!first && lane < 8)
        hv = *reinterpret_cast<const float4*>(x + wbase - 32 + 4 * lane);

    float4 v[ROWS];
    if (full) {
        #pragma unroll
        for (int r = 0; r < ROWS; r++)
            v[r] = __ldcs(reinterpret_cast<const float4*>(
                       x + wbase + r * ROWE + 4 * lane));
    } else {
        #pragma unroll
        for (int r = 0; r < ROWS; r++) {
            long g = wbase + r * ROWE + 4 * lane;
            v[r].x = (g + 0 < n) ? x[g + 0] : 0.0f;
            v[r].y = (g + 1 < n) ? x[g + 1] : 0.0f;
            v[r].z = (g + 2 < n) ? x[g + 2] : 0.0f;
            v[r].w = (g + 3 < n) ? x[g + 3] : 0.0f;
        }
    }

    // ---- warp seed: scan the 32-element halo (lanes 0-7 hold data) ----
    float cw;
    if (first) {
        cw = __ldg(x);                       // exact: y_{-1} = x[0]
    } else {
        float hS = (lane < 8) ? d * horner4(a, hv) : 0.0f;
        float m;
        m = __shfl_up_sync(0xffffffffu, hS, 1);
        if (lane >= 1) hS = fmaf(p4, m, hS);
        m = __shfl_up_sync(0xffffffffu, hS, 2);
        if (lane >= 2) hS = fmaf(p8, m, hS);
        m = __shfl_up_sync(0xffffffffu, hS, 4);
        if (lane >= 4) hS = fmaf(p16, m, hS);
        cw = __shfl_sync(0xffffffffu, hS, 7);   // carry entering warp region
    }

    // ---- per-lane factor f = a^(4*lane)  (underflows to 0 for lane >= 16) ----
    float f = 1.0f, b = p4;
    if (lane & 1)  f *= b;  b *= b;
    if (lane & 2)  f *= b;  b *= b;
    if (lane & 4)  f *= b;  b *= b;
    if (lane & 8)  f *= b;  b *= b;
    if (lane & 16) f *= b;

    // ---- row scans: independent across rows (ILP), carry chain 1 shfl/row ----
    #pragma unroll
    for (int r = 0; r < ROWS; r++) {
        float S = d * horner4(a, v[r]);
        float t;
        t = __shfl_up_sync(0xffffffffu, S, 1);
        if (lane >= 1) S = fmaf(p4, t, S);
        t = __shfl_up_sync(0xffffffffu, S, 2);
        if (lane >= 2) S = fmaf(p8, t, S);
        t = __shfl_up_sync(0xffffffffu, S, 4);
        if (lane >= 4) S = fmaf(p16, t, S);

        float E = __shfl_up_sync(0xffffffffu, S, 1);
        if (lane == 0) E = 0.0f;
        float c = fmaf(f, cw, E);           // carry entering own 4 elements

        float y0 = fmaf(a, c,  d * v[r].x);
        float y1 = fmaf(a, y0, d * v[r].y);
        float y2 = fmaf(a, y1, d * v[r].z);
        float y3 = fmaf(a, y2, d * v[r].w);

        cw = __shfl_sync(0xffffffffu, S, 31);   // carry_out: indep of carry_in

        long g = wbase + r * ROWE + 4 * lane;
        if (full) {
            __stcs(reinterpret_cast<float4*>(out + g),
                   make_float4(y0, y1, y2, y3));
        } else {
            if (g + 0 < n) out[g + 0] = y0;
            if (g + 1 < n) out[g + 1] = y1;
            if (g + 2 < n) out[g + 2] = y2;
            if (g + 3 < n) out[g + 3] = y3;
        }
    }
}

extern "C" void kernel_launch(void* const* d_in, const int* in_sizes, int n_in,
                              void* d_out, int out_size)
{
    const float* x     = (const float*)d_in[0];
    const float* decay = (const float*)d_in[1];
    float*       out   = (float*)d_out;
    const int    n     = in_sizes[0];

    const int nblocks = (n + TILE - 1) / TILE;
    ema_kernel<<<nblocks, NT>>>(x, decay, out, n);
}

// round 7
// speedup vs baseline: 1.2805x; 1.0137x over previous
#include <cuda_runtime.h>

// EMA scan: y_t = d*x_t + (1-d)*y_{t-1}, y_{-1} = x[0], d = 0.9 (a = 0.1).
//
// Warp-independent, zero smem / zero barriers:
//  - Each warp owns 512 consecutive elements = 4 rows x (32 lanes x float4).
//  - All 4 row loads + halo issued up front (MLP = 5/warp); high occupancy
//    (6+ CTAs/SM) supplies chip-level memory parallelism.
//  - Lookback is truncated at 16 elements (a^16 = 1e-16, 8 orders below fp32
//    eps): Kogge-Stone needs only steps {1,2}; lanes >= 4 ignore the warp
//    carry entirely.
//  - Row carry_out = lane-31 inclusive value (independent of carry_in) ->
//    rows are ILP-parallel, cross-row chain is one broadcast shuffle.

#define NT    256
#define ROWS  4
#define ROWE  128                 // elements per row (32 lanes * 4)
#define WREG  (ROWS * ROWE)       // 512 elements per warp
#define TILE  ((NT / 32) * WREG)  // 4096 elements per block

__device__ __forceinline__ float horner4(float a, float4 v) {
    float h = v.x;
    h = fmaf(a, h, v.y);
    h = fmaf(a, h, v.z);
    h = fmaf(a, h, v.w);
    return h;
}

__global__ __launch_bounds__(NT, 6)
void ema_kernel(const float* __restrict__ x,
                const float* __restrict__ decay_p,
                float* __restrict__ out, int n)
{
    const float d  = __ldg(decay_p);
    const float a  = 1.0f - d;
    const float a2 = a * a;
    const float p4 = a2 * a2;      // a^4
    const float p8 = p4 * p4;      // a^8

    const int lane  = threadIdx.x & 31;
    const int wid   = threadIdx.x >> 5;
    const int wbase = blockIdx.x * TILE + wid * WREG;
    const bool full  = (wbase + WREG) <= n;
    const bool first = (wbase == 0);

    // ---- issue all loads up front: 16-elem halo + 4 rows (MLP = 5) ----
    float4 hv = make_float4(0.f, 0.f, 0.f, 0.f);
    if (!first && lane < 4)
        hv = *reinterpret_cast<const float4*>(x + wbase - 16 + 4 * lane);

    float4 v[ROWS];
    if (full) {
        #pragma unroll
        for (int r = 0; r < ROWS; r++)
            v[r] = *reinterpret_cast<const float4*>(
                       x + wbase + r * ROWE + 4 * lane);
    } else {
        #pragma unroll
        for (int r = 0; r < ROWS; r++) {
            int g = wbase + r * ROWE + 4 * lane;
            v[r].x = (g + 0 < n) ? x[g + 0] : 0.0f;
            v[r].y = (g + 1 < n) ? x[g + 1] : 0.0f;
            v[r].z = (g + 2 < n) ? x[g + 2] : 0.0f;
            v[r].w = (g + 3 < n) ? x[g + 3] : 0.0f;
        }
    }

    // ---- warp seed: scan the 16-element halo (lanes 0-3 hold data) ----
    float cw;
    if (first) {
        cw = __ldg(x);                       // exact: y_{-1} = x[0]
    } else {
        float hS = (lane < 4) ? d * horner4(a, hv) : 0.0f;
        float m;
        m = __shfl_up_sync(0xffffffffu, hS, 1);
        if (lane >= 1) hS = fmaf(p4, m, hS);
        m = __shfl_up_sync(0xffffffffu, hS, 2);
        if (lane >= 2) hS = fmaf(p8, m, hS);
        cw = __shfl_sync(0xffffffffu, hS, 3);   // carry entering warp region
    }

    // ---- per-lane factor f = a^(4*lane), truncated to 0 for lane >= 4 ----
    float f = 0.0f;
    if (lane < 4)
        f = ((lane & 1) ? p4 : 1.0f) * ((lane & 2) ? p8 : 1.0f);

    // ---- row scans: ILP-parallel, cross-row chain = 1 broadcast shuffle ----
    #pragma unroll
    for (int r = 0; r < ROWS; r++) {
        float S = d * horner4(a, v[r]);
        float t;
        t = __shfl_up_sync(0xffffffffu, S, 1);
        if (lane >= 1) S = fmaf(p4, t, S);
        t = __shfl_up_sync(0xffffffffu, S, 2);
        if (lane >= 2) S = fmaf(p8, t, S);
        // S now covers lanes r-3..r (16 elements) — sufficient lookback.

        float E = __shfl_up_sync(0xffffffffu, S, 1);
        if (lane == 0) E = 0.0f;
        float c = fmaf(f, cw, E);            // carry entering own 4 elements

        float y0 = fmaf(a, c,  d * v[r].x);
        float y1 = fmaf(a, y0, d * v[r].y);
        float y2 = fmaf(a, y1, d * v[r].z);
        float y3 = fmaf(a, y2, d * v[r].w);

        cw = __shfl_sync(0xffffffffu, S, 31);   // carry_out (indep of carry_in)

        int g = wbase + r * ROWE + 4 * lane;
        if (full) {
            __stcs(reinterpret_cast<float4*>(out + g),
                   make_float4(y0, y1, y2, y3));
        } else {
            if (g + 0 < n) out[g + 0] = y0;
            if (g + 1 < n) out[g + 1] = y1;
            if (g + 2 < n) out[g + 2] = y2;
            if (g + 3 < n) out[g + 3] = y3;
        }
    }
}

extern "C" void kernel_launch(void* const* d_in, const int* in_sizes, int n_in,
                              void* d_out, int out_size)
{
    const float* x     = (const float*)d_in[0];
    const float* decay = (const float*)d_in[1];
    float*       out   = (float*)d_out;
    const int    n     = in_sizes[0];

    const int nblocks = (n + TILE - 1) / TILE;
    ema_kernel<<<nblocks, NT>>>(x, decay, out, n);
}

// round 8
// speedup vs baseline: 1.3977x; 1.0915x over previous
#include <cuda_runtime.h>

// EMA scan: y_t = d*x_t + (1-d)*y_{t-1}, y_{-1} = x[0], d = 0.9 (a = 0.1).
//
// Persistent software-pipelined warps, zero smem / zero barriers:
//  - Each warp processes 512-element segments (4 rows x 32 lanes x float4).
//  - Loads for segment i+1 (4 rows + 16-elem halo) are issued BEFORE the
//    compute of segment i -> memory latency hidden behind compute.
//  - Lookback truncated at 16 elements (a^16 = 1e-16, far below fp32 eps):
//    Kogge-Stone steps {1,2} only; lanes >= 4 ignore the warp carry (f=0).
//  - Row carry_out = lane-31 inclusive value (a^128 == 0 -> independent of
//    carry_in), so rows are ILP-parallel.

#define NT    256
#define NW    (NT / 32)
#define ROWS  4
#define ROWE  128                 // elements per row
#define WREG  (ROWS * ROWE)       // 512 elements per warp
#define TILE  (NW * WREG)         // 4096 elements per block-segment

__device__ __forceinline__ float horner4(float a, float4 w) {
    float h = w.x;
    h = fmaf(a, h, w.y);
    h = fmaf(a, h, w.z);
    h = fmaf(a, h, w.w);
    return h;
}

__device__ __forceinline__ void load_seg(const float* __restrict__ x, int n,
                                         int wbase, int lane,
                                         float4 v[ROWS], float4& hv)
{
    hv = make_float4(0.f, 0.f, 0.f, 0.f);
    if (wbase != 0 && wbase <= n && lane < 4)
        hv = *reinterpret_cast<const float4*>(x + wbase - 16 + 4 * lane);

    if (wbase + WREG <= n) {
        #pragma unroll
        for (int r = 0; r < ROWS; r++)
            v[r] = *reinterpret_cast<const float4*>(
                       x + wbase + r * ROWE + 4 * lane);
    } else {
        #pragma unroll
        for (int r = 0; r < ROWS; r++) {
            int g = wbase + r * ROWE + 4 * lane;
            v[r].x = (g + 0 < n) ? x[g + 0] : 0.0f;
            v[r].y = (g + 1 < n) ? x[g + 1] : 0.0f;
            v[r].z = (g + 2 < n) ? x[g + 2] : 0.0f;
            v[r].w = (g + 3 < n) ? x[g + 3] : 0.0f;
        }
    }
}

__device__ __forceinline__ void process_seg(const float* __restrict__ x,
                                            float* __restrict__ out, int n,
                                            int wbase, int lane,
                                            float d, float a, float p4, float p8,
                                            float f,
                                            const float4 v[ROWS], float4 hv)
{
    // incoming warp carry from the 16-element halo
    float cw;
    if (wbase == 0) {
        cw = __ldg(x);                          // exact: y_{-1} = x[0]
    } else {
        float hS = 0.0f;
        if (lane < 4) {
            float4 w = make_float4(d * hv.x, d * hv.y, d * hv.z, d * hv.w);
            hS = horner4(a, w);
        }
        float m;
        m = __shfl_up_sync(0xffffffffu, hS, 1);
        if (lane >= 1) hS = fmaf(p4, m, hS);
        m = __shfl_up_sync(0xffffffffu, hS, 2);
        if (lane >= 2) hS = fmaf(p8, m, hS);
        cw = __shfl_sync(0xffffffffu, hS, 3);
    }

    const bool full = (wbase + WREG <= n);

    #pragma unroll
    for (int r = 0; r < ROWS; r++) {
        float4 w = make_float4(d * v[r].x, d * v[r].y, d * v[r].z, d * v[r].w);
        float S = horner4(a, w);
        float t;
        t = __shfl_up_sync(0xffffffffu, S, 1);
        if (lane >= 1) S = fmaf(p4, t, S);
        t = __shfl_up_sync(0xffffffffu, S, 2);
        if (lane >= 2) S = fmaf(p8, t, S);
        // S covers lanes r-3..r (16 elements) — full required lookback.

        float E = __shfl_up_sync(0xffffffffu, S, 1);
        if (lane == 0) E = 0.0f;
        float c = fmaf(f, cw, E);               // carry entering own 4 elems

        float y0 = fmaf(a, c,  w.x);
        float y1 = fmaf(a, y0, w.y);
        float y2 = fmaf(a, y1, w.z);
        float y3 = fmaf(a, y2, w.w);

        cw = __shfl_sync(0xffffffffu, S, 31);   // carry_out (indep of carry_in)

        int g = wbase + r * ROWE + 4 * lane;
        if (full) {
            __stcs(reinterpret_cast<float4*>(out + g),
                   make_float4(y0, y1, y2, y3));
        } else {
            if (g + 0 < n) out[g + 0] = y0;
            if (g + 1 < n) out[g + 1] = y1;
            if (g + 2 < n) out[g + 2] = y2;
            if (g + 3 < n) out[g + 3] = y3;
        }
    }
}

__global__ __launch_bounds__(NT, 4)
void ema_kernel(const float* __restrict__ x,
                const float* __restrict__ decay_p,
                float* __restrict__ out, int n, int nseg)
{
    const float d  = __ldg(decay_p);
    const float a  = 1.0f - d;
    const float a2 = a * a;
    const float p4 = a2 * a2;
    const float p8 = p4 * p4;

    const int lane = threadIdx.x & 31;
    const int wid  = threadIdx.x >> 5;
    const int stride = gridDim.x;

    // per-lane carry factor a^(4*lane), truncated to 0 for lane >= 4
    float f = 0.0f;
    if (lane < 4)
        f = ((lane & 1) ? p4 : 1.0f) * ((lane & 2) ? p8 : 1.0f);

    int seg = blockIdx.x;
    if (seg >= nseg) return;

    int wbase = seg * TILE + wid * WREG;
    float4 vc[ROWS], hc;
    load_seg(x, n, wbase, lane, vc, hc);

    for (;;) {
        const int seg2 = seg + stride;
        const bool have_next = (seg2 < nseg);

        float4 vn[ROWS], hn;
        int wbase2 = seg2 * TILE + wid * WREG;
        if (have_next)
            load_seg(x, n, wbase2, lane, vn, hn);   // prefetch next segment

        process_seg(x, out, n, wbase, lane, d, a, p4, p8, f, vc, hc);

        if (!have_next) break;
        #pragma unroll
        for (int r = 0; r < ROWS; r++) vc[r] = vn[r];
        hc = hn;
        wbase = wbase2;
        seg = seg2;
    }
}

extern "C" void kernel_launch(void* const* d_in, const int* in_sizes, int n_in,
                              void* d_out, int out_size)
{
    const float* x     = (const float*)d_in[0];
    const float* decay = (const float*)d_in[1];
    float*       out   = (float*)d_out;
    const int    n     = in_sizes[0];

    const int nseg = (n + TILE - 1) / TILE;
    int grid = 148 * 4;                 // persistent: 4 CTAs/SM on 148 SMs
    if (grid > nseg) grid = nseg;
    ema_kernel<<<grid, NT>>>(x, decay, out, n, nseg);
}